// round 15
// baseline (speedup 1.0000x reference)
#include <cuda_runtime.h>
#include <cuda_bf16.h>
#include <math.h>

#define NT   4096
#define NAr  4096
#define NSr  1024
#define NALL 9216
#define FEAT 128
#define COM  64
#define MPD  64
#define NCLS 3
#define CAP  128   // max nnz per adjacency row (expected ~20, p=0.005)

// ---------------- static device scratch (no allocations allowed) -------------
__device__ float g_big[7ll * NT * NT];

// bf16 3-way split feature buffers for tensor-core sims (7 jobs, K<=256)
__device__ __nv_bfloat16 g_bf1[7ll * NT * 256];
__device__ __nv_bfloat16 g_bf2[7ll * NT * 256];
__device__ __nv_bfloat16 g_bf3[7ll * NT * 256];

#define OFF_SIMS  0                         // 1024*1024
#define OFF_FPA   (OFF_SIMS + NSr*NSr)      // 4096*128
#define OFF_FPS   (OFF_FPA  + NT*FEAT)      // 4096*128
#define OFF_THA   (OFF_FPS  + NT*FEAT)      // 4096*64
#define OFF_THS   (OFF_THA  + NT*COM)       // 4096*64
#define OFF_SWA   (OFF_THS  + NT*COM)       // 4096*64
#define OFF_SWS   (OFF_SWA  + NT*COM)       // 1024*64
#define OFF_H0    (OFF_SWS  + NSr*COM)      // 4096*64
#define OFF_X1    (OFF_H0   + NT*COM)       // 4096*64
#define OFF_H2    (OFF_X1   + NT*COM)       // 4096*3
#define OFF_CS    (OFF_H2   + NT*NCLS)      // 7*4096
#define OFF_COEF  (OFF_CS   + 7*NT)         // 7*4096
#define OFF_CT    (OFF_COEF + 7*NT)         // 4096
#define OFF_PART2 (OFF_CT   + NT)           // 64*4096 row partials
#define OFF_CSP   (OFF_PART2+ 64*NT)        // 7*32*4096
#define OFF_SPART (OFF_CSP  + 7*32*NT)      // 8*4096*64
#define SMALL_TOT (OFF_SPART + 8*NT*64)
__device__ float g_small[SMALL_TOT];

#define OFF_IDXA 0
#define OFF_CNTA (OFF_IDXA + NT*CAP)
#define OFF_IDXS (OFF_CNTA + NT)
#define OFF_CNTS (OFF_IDXS + NT*CAP)
#define IBUF_TOT (OFF_CNTS + NT)
__device__ int g_ibuf[IBUF_TOT];

// ---------------- packed f32x2 helpers ----------------
typedef unsigned long long u64t;

__device__ __forceinline__ u64t bcast2(float a)
{
    u64t r;
    asm("mov.b64 %0, {%1, %1};" : "=l"(r) : "r"(__float_as_uint(a)));
    return r;
}
__device__ __forceinline__ void fma2(u64t& acc, u64t a, u64t b)
{
    asm("fma.rn.f32x2 %0, %1, %2, %0;" : "+l"(acc) : "l"(a), "l"(b));
}
__device__ __forceinline__ float2 unpack2(u64t v)
{
    unsigned int lo, hi;
    asm("mov.b64 {%0, %1}, %2;" : "=r"(lo), "=r"(hi) : "l"(v));
    return make_float2(__uint_as_float(lo), __uint_as_float(hi));
}

// ---------------- tensor-core helpers ----------------
#define LDSM4(d, addr) \
    asm volatile("ldmatrix.sync.aligned.m8n8.x4.shared.b16 {%0,%1,%2,%3}, [%4];" \
                 : "=r"((d)[0]), "=r"((d)[1]), "=r"((d)[2]), "=r"((d)[3]) : "r"(addr))

#define MMA16816(c, a, b0, b1) \
    asm volatile("mma.sync.aligned.m16n8k16.row.col.f32.bf16.bf16.f32 " \
                 "{%0,%1,%2,%3},{%4,%5,%6,%7},{%8,%9},{%0,%1,%2,%3};" \
                 : "+f"((c)[0]), "+f"((c)[1]), "+f"((c)[2]), "+f"((c)[3]) \
                 : "r"((a)[0]), "r"((a)[1]), "r"((a)[2]), "r"((a)[3]), "r"(b0), "r"(b1))

// ---------------- job structs (passed by value as kernel args) ---------------
struct PrepJob { const float* src; const float* w;
                 __nv_bfloat16* d1; __nv_bfloat16* d2; __nv_bfloat16* d3; int N; int D; };
struct PrepJobs { PrepJob j[7]; };
struct SimJob  { const __nv_bfloat16* X1; const __nv_bfloat16* X2; const __nv_bfloat16* X3;
                 float* C; float* cs; int N; int K; int nBlk; float th; int mirror; };
struct SimJobs { SimJob j[7]; };

// ---------------- kernels ----------------------------------------------------

// Multi-job per-head weighted + L2-row-normalized features as a 3-way bf16
// split: v = d1 + d2 + d3 with residual <= 2^-27 |v|. Uses division (matching
// the reference's elementwise x / norm). Layout [N][2*D].
__global__ void prep_norm_multi_kernel(PrepJobs jobs)
{
    PrepJob jb = jobs.j[blockIdx.y];
    int row  = blockIdx.x * (blockDim.x >> 5) + (threadIdx.x >> 5);
    int lane = threadIdx.x & 31;
    if (row >= jb.N) return;
    const float* src = jb.src;
    const float* w   = jb.w;
    int D = jb.D;
    int HD = 2 * D;
    for (int h = 0; h < 2; h++) {
        float ss = 0.f;
        for (int d = lane; d < D; d += 32) {
            float v = src[(size_t)row * D + d] * w[h * D + d];
            ss += v * v;
        }
        #pragma unroll
        for (int o = 16; o; o >>= 1) ss += __shfl_xor_sync(0xffffffffu, ss, o);
        float nrm = fmaxf(sqrtf(ss), 1e-12f);
        for (int d = lane; d < D; d += 32) {
            float v = (src[(size_t)row * D + d] * w[h * D + d]) / nrm;
            __nv_bfloat16 h1 = __float2bfloat16(v);
            float v1 = v - __bfloat162float(h1);
            __nv_bfloat16 h2 = __float2bfloat16(v1);
            float v2 = v1 - __bfloat162float(h2);
            __nv_bfloat16 h3 = __float2bfloat16(v2);
            size_t e = (size_t)row * HD + h * D + d;
            jb.d1[e] = h1;
            jb.d2[e] = h2;
            jb.d3[e] = h3;
        }
    }
}

__device__ __forceinline__ float thrf(float v, float scale, float th)
{
    v *= scale;
    return (v < th) ? 0.f : v;
}

// Multi-job C = threshold(0.5 * X @ X^T) via 3-way bf16 tensor-core MMA with
// SPLIT ACCUMULATORS: main plane h1*h1 -> accM (only 16 full-scale roundings);
// correction planes (h1h2, h2h1, h2h2, h1h3, h3h1) -> accC whose magnitude is
// ~2^-9, so its roundings are absolutely negligible. acc = accM + accC.
// Total error ~3e-7, ~3x below the sequential-fp32 FFMA chain.
__global__ void __launch_bounds__(256, 1)
simgemm_tc_multi_kernel(SimJobs jobs)
{
    SimJob jb = jobs.j[blockIdx.y];
    const int nBlk = jb.nBlk;
    int idx = blockIdx.x;
    if (idx >= nBlk * (nBlk + 1) / 2) return;

    float nb2 = nBlk + 0.5f;
    int by = (int)(nb2 - sqrtf(fmaxf(nb2 * nb2 - 2.0f * idx, 0.f)));
    if (by < 0) by = 0;
    if (by > nBlk - 1) by = nBlk - 1;
    while (by > 0 && (by * nBlk - (by * (by - 1)) / 2) > idx) by--;
    while (((by + 1) * nBlk - ((by + 1) * by) / 2) <= idx) by++;
    int bx = by + (idx - (by * nBlk - (by * (by - 1)) / 2));

    const int m0 = by * 128, n0 = bx * 128;
    const int N = jb.N, K = jb.K;

    __shared__ __align__(16) __nv_bfloat16 A1[128][24];
    __shared__ __align__(16) __nv_bfloat16 A2[128][24];
    __shared__ __align__(16) __nv_bfloat16 A3[128][24];
    __shared__ __align__(16) __nv_bfloat16 B1[128][24];
    __shared__ __align__(16) __nv_bfloat16 B2[128][24];
    __shared__ __align__(16) __nv_bfloat16 B3[128][24];

    const int tid = threadIdx.x;
    const int wrp = tid >> 5, ln = tid & 31;
    const int wm = wrp & 3, wn = wrp >> 2;   // 4 x 2 warp grid

    float accM[2][8][4], accC[2][8][4];
    #pragma unroll
    for (int mi = 0; mi < 2; mi++)
        #pragma unroll
        for (int ni = 0; ni < 8; ni++)
            #pragma unroll
            for (int t = 0; t < 4; t++) { accM[mi][ni][t] = 0.f; accC[mi][ni][t] = 0.f; }

    const int lrow = ln & 15;
    const int lk8  = (ln >> 4) << 3;
    const int lrw  = tid >> 1;           // 0..127 loader row
    const int lq   = (tid & 1) << 3;     // 0 or 8

    for (int k0 = 0; k0 < K; k0 += 16) {
        __syncthreads();
        {
            size_t ea = (size_t)(m0 + lrw) * K + k0 + lq;
            size_t eb = (size_t)(n0 + lrw) * K + k0 + lq;
            *(uint4*)&A1[lrw][lq] = *(const uint4*)(jb.X1 + ea);
            *(uint4*)&A2[lrw][lq] = *(const uint4*)(jb.X2 + ea);
            *(uint4*)&A3[lrw][lq] = *(const uint4*)(jb.X3 + ea);
            *(uint4*)&B1[lrw][lq] = *(const uint4*)(jb.X1 + eb);
            *(uint4*)&B2[lrw][lq] = *(const uint4*)(jb.X2 + eb);
            *(uint4*)&B3[lrw][lq] = *(const uint4*)(jb.X3 + eb);
        }
        __syncthreads();

        unsigned int a1[2][4], a2[2][4], a3[2][4];
        #pragma unroll
        for (int mi = 0; mi < 2; mi++) {
            int arow = wm * 32 + mi * 16 + lrow;
            LDSM4(a1[mi], (unsigned)__cvta_generic_to_shared(&A1[arow][lk8]));
            LDSM4(a2[mi], (unsigned)__cvta_generic_to_shared(&A2[arow][lk8]));
            LDSM4(a3[mi], (unsigned)__cvta_generic_to_shared(&A3[arow][lk8]));
        }
        #pragma unroll
        for (int np = 0; np < 4; np++) {
            unsigned int b1[4], b2[4], b3[4];
            int brow = wn * 64 + np * 16 + lrow;
            LDSM4(b1, (unsigned)__cvta_generic_to_shared(&B1[brow][lk8]));
            LDSM4(b2, (unsigned)__cvta_generic_to_shared(&B2[brow][lk8]));
            LDSM4(b3, (unsigned)__cvta_generic_to_shared(&B3[brow][lk8]));
            #pragma unroll
            for (int bi = 0; bi < 2; bi++) {
                unsigned int b1a = bi ? b1[1] : b1[0], b1b = bi ? b1[3] : b1[2];
                unsigned int b2a = bi ? b2[1] : b2[0], b2b = bi ? b2[3] : b2[2];
                unsigned int b3a = bi ? b3[1] : b3[0], b3b = bi ? b3[3] : b3[2];
                int ni = np * 2 + bi;
                #pragma unroll
                for (int mi = 0; mi < 2; mi++) {
                    MMA16816(accM[mi][ni], a1[mi], b1a, b1b);   // h1*h1 (main)
                    MMA16816(accC[mi][ni], a1[mi], b2a, b2b);   // h1*h2
                    MMA16816(accC[mi][ni], a2[mi], b1a, b1b);   // h2*h1
                    MMA16816(accC[mi][ni], a2[mi], b2a, b2b);   // h2*h2
                    MMA16816(accC[mi][ni], a1[mi], b3a, b3b);   // h1*h3
                    MMA16816(accC[mi][ni], a3[mi], b1a, b1b);   // h3*h1
                }
            }
        }
    }

    // combine planes + threshold
    const float th = jb.th;
    float acc[2][8][4];
    #pragma unroll
    for (int mi = 0; mi < 2; mi++)
        #pragma unroll
        for (int ni = 0; ni < 8; ni++)
            #pragma unroll
            for (int t = 0; t < 4; t++)
                acc[mi][ni][t] = thrf(accM[mi][ni][t] + accC[mi][ni][t], 0.5f, th);

    float* C = jb.C;
    const int r  = ln >> 2;
    const int cp = (ln & 3) << 1;

    // direct stores
    #pragma unroll
    for (int mi = 0; mi < 2; mi++) {
        int g = m0 + wm * 32 + mi * 16 + r;
        #pragma unroll
        for (int ni = 0; ni < 8; ni++) {
            int gc = n0 + wn * 64 + ni * 8 + cp;
            *(float2*)&C[(size_t)g * N + gc]       = make_float2(acc[mi][ni][0], acc[mi][ni][1]);
            *(float2*)&C[(size_t)(g + 8) * N + gc] = make_float2(acc[mi][ni][2], acc[mi][ni][3]);
        }
    }
    if (bx > by && jb.mirror) {
        #pragma unroll
        for (int mi = 0; mi < 2; mi++) {
            int g = m0 + wm * 32 + mi * 16 + r;
            #pragma unroll
            for (int ni = 0; ni < 8; ni++) {
                int gc = n0 + wn * 64 + ni * 8 + cp;
                C[(size_t)gc * N + g]           = acc[mi][ni][0];
                C[(size_t)(gc + 1) * N + g]     = acc[mi][ni][1];
                C[(size_t)gc * N + g + 8]       = acc[mi][ni][2];
                C[(size_t)(gc + 1) * N + g + 8] = acc[mi][ni][3];
            }
        }
    }

    if (jb.cs) {
        __syncthreads();
        float* red = (float*)A1;   // reuse smem (768 floats needed; 6 tiles available)
        #pragma unroll
        for (int ni = 0; ni < 8; ni++) {
            float s0 = acc[0][ni][0] + acc[0][ni][2] + acc[1][ni][0] + acc[1][ni][2];
            float s1 = acc[0][ni][1] + acc[0][ni][3] + acc[1][ni][1] + acc[1][ni][3];
            s0 += __shfl_xor_sync(0xffffffffu, s0, 4);
            s0 += __shfl_xor_sync(0xffffffffu, s0, 8);
            s0 += __shfl_xor_sync(0xffffffffu, s0, 16);
            s1 += __shfl_xor_sync(0xffffffffu, s1, 4);
            s1 += __shfl_xor_sync(0xffffffffu, s1, 8);
            s1 += __shfl_xor_sync(0xffffffffu, s1, 16);
            if (ln < 4) {
                red[wm * 128 + wn * 64 + ni * 8 + cp]     = s0;
                red[wm * 128 + wn * 64 + ni * 8 + cp + 1] = s1;
            }
        }
        #pragma unroll
        for (int mi = 0; mi < 2; mi++) {
            float r0 = 0.f, r1 = 0.f;
            #pragma unroll
            for (int ni = 0; ni < 8; ni++) {
                r0 += acc[mi][ni][0] + acc[mi][ni][1];
                r1 += acc[mi][ni][2] + acc[mi][ni][3];
            }
            r0 += __shfl_xor_sync(0xffffffffu, r0, 1);
            r0 += __shfl_xor_sync(0xffffffffu, r0, 2);
            r1 += __shfl_xor_sync(0xffffffffu, r1, 1);
            r1 += __shfl_xor_sync(0xffffffffu, r1, 2);
            if ((ln & 3) == 0) {
                red[512 + wn * 128 + wm * 32 + mi * 16 + r]     = r0;
                red[512 + wn * 128 + wm * 32 + mi * 16 + r + 8] = r1;
            }
        }
        __syncthreads();
        if (tid < 128) {
            float s = red[tid] + red[128 + tid] + red[256 + tid] + red[384 + tid];
            jb.cs[(size_t)by * N + n0 + tid] = s;
        }
        if (bx > by && tid >= 128 && tid < 256) {
            int rr = tid - 128;
            jb.cs[(size_t)bx * N + m0 + rr] = red[512 + rr] + red[640 + rr];
        }
    }
}

// Deterministic ballot-compacted nonzero index list; 4 warps scan disjoint
// segments, merged in segment order.
__global__ void build_idx_kernel(const float* __restrict__ adj, int col_off, int NR,
                                 int* __restrict__ idx, int* __restrict__ cnt)
{
    __shared__ int sidx[4][CAP];
    __shared__ int scnt[4];
    int i = blockIdx.x;
    const float* r = adj + (size_t)i * NALL + col_off;
    int w = threadIdx.x >> 5, lane = threadIdx.x & 31;
    int seg = NR >> 2;
    int b0  = w * seg;
    int count = 0;
    for (int base = b0; base < b0 + seg; base += 32) {
        float v = r[base + lane];
        unsigned m = __ballot_sync(0xffffffffu, v != 0.f);
        int pre = __popc(m & ((1u << lane) - 1u));
        if (v != 0.f && (count + pre) < CAP) sidx[w][count + pre] = base + lane;
        count += __popc(m);
    }
    if (lane == 0) scnt[w] = min(count, CAP);
    __syncthreads();
    int myoff = 0, tot = 0;
    #pragma unroll
    for (int p = 0; p < 4; p++) {
        if (p < w) myoff += scnt[p];
        tot += scnt[p];
    }
    for (int t = lane; t < scnt[w]; t += 32) {
        int pos = myoff + t;
        if (pos < CAP) idx[(size_t)i * CAP + pos] = sidx[w][t];
    }
    if (threadIdx.x == 0) cnt[i] = min(tot, CAP);
}

__global__ void gather_sum_kernel(const float* __restrict__ src, int lds,
                                  const int* __restrict__ idx, const int* __restrict__ cnt,
                                  float* __restrict__ out, int ldo)
{
    int i = blockIdx.y;
    int j = ((blockIdx.x * blockDim.x + threadIdx.x) << 2);
    int c = cnt[i];
    const int* ip = idx + (size_t)i * CAP;
    float4 s = make_float4(0.f, 0.f, 0.f, 0.f);
    for (int t = 0; t < c; t++) {
        float4 v = *(const float4*)(src + (size_t)ip[t] * lds + j);
        s.x += v.x; s.y += v.y; s.z += v.z; s.w += v.w;
    }
    *(float4*)(out + (size_t)i * ldo + j) = s;
}

__global__ void gather64b_kernel(const float* __restrict__ src,
                                 const int* __restrict__ idx, const int* __restrict__ cnt,
                                 const float* __restrict__ bias, float* __restrict__ out)
{
    int i = blockIdx.x;
    int c = threadIdx.x;
    int n = cnt[i];
    const int* ip = idx + (size_t)i * CAP;
    float s = 0.f;
    for (int t = 0; t < n; t++) s += src[(size_t)ip[t] * 64 + c];
    out[(size_t)i * 64 + c] = s + bias[c];
}

// C[M,64] = A[M,K] @ B[K,64] (+bias) (optional relu) — 64x64 tile, for small K
__global__ void __launch_bounds__(256)
gemm_n64_kernel(const float* __restrict__ A, const float* __restrict__ B,
                const float* __restrict__ bias, float* __restrict__ C,
                int M, int K, int relu)
{
    __shared__ float As[32][64];
    __shared__ float Bs[32][64];
    int tid = threadIdx.x;
    int m0  = blockIdx.x * 64;
    int ar  = tid >> 3;
    int ac  = (tid & 7) << 2;
    int br  = tid >> 4;
    int bc  = (tid & 15) << 2;
    int wrp = tid >> 5, ln = tid & 31;
    int ty  = ((wrp >> 1) << 2) | (ln >> 3);
    int tx  = ((wrp & 1) << 3) | (ln & 7);

    u64t acc2[4][2];
    #pragma unroll
    for (int i = 0; i < 4; i++) { acc2[i][0] = 0ull; acc2[i][1] = 0ull; }

    for (int k0 = 0; k0 < K; k0 += 32) {
        float4 a0 = *(const float4*)(A + (size_t)(m0 + ar)      * K + k0 + ac);
        float4 a1 = *(const float4*)(A + (size_t)(m0 + ar + 32) * K + k0 + ac);
        float4 b0 = *(const float4*)(B + (size_t)(k0 + br)      * 64 + bc);
        float4 b1 = *(const float4*)(B + (size_t)(k0 + br + 16) * 64 + bc);
        __syncthreads();
        As[ac+0][ar]    = a0.x; As[ac+1][ar]    = a0.y; As[ac+2][ar]    = a0.z; As[ac+3][ar]    = a0.w;
        As[ac+0][ar+32] = a1.x; As[ac+1][ar+32] = a1.y; As[ac+2][ar+32] = a1.z; As[ac+3][ar+32] = a1.w;
        *(float4*)&Bs[br][bc]      = b0;
        *(float4*)&Bs[br + 16][bc] = b1;
        __syncthreads();
        #pragma unroll
        for (int k = 0; k < 32; k++) {
            float4 av = *(const float4*)&As[k][ty << 2];
            float4 bv = *(const float4*)&Bs[k][tx << 2];
            u64t bp0 = ((const u64t*)&bv)[0], bp1 = ((const u64t*)&bv)[1];
            float a[4] = {av.x, av.y, av.z, av.w};
            #pragma unroll
            for (int i = 0; i < 4; i++) {
                u64t ai = bcast2(a[i]);
                fma2(acc2[i][0], ai, bp0);
                fma2(acc2[i][1], ai, bp1);
            }
        }
    }
    int r = m0 + (ty << 2), c = tx << 2;
    #pragma unroll
    for (int i = 0; i < 4; i++) {
        float2 v0 = unpack2(acc2[i][0]);
        float2 v1 = unpack2(acc2[i][1]);
        float vv[4] = {v0.x, v0.y, v1.x, v1.y};
        #pragma unroll
        for (int j = 0; j < 4; j++) {
            float v = vv[j] + (bias ? bias[c + j] : 0.f);
            if (relu) v = fmaxf(v, 0.f);
            C[(size_t)(r + i) * 64 + c + j] = v;
        }
    }
}

// split-K GEMM, 128x64 tile, 8x4 per thread. grid (M/128, S).
__global__ void __launch_bounds__(256)
gemm128_splitk_kernel(const float* __restrict__ A, const float* __restrict__ B,
                      float* __restrict__ part, int M, int K, int Kc)
{
    __shared__ float As[32][128];
    __shared__ float Bs[32][64];
    int tid = threadIdx.x;
    int m0  = blockIdx.x * 128;
    int s   = blockIdx.y;
    int kb  = s * Kc, ke = kb + Kc;
    int ar  = tid >> 1;
    int ac  = (tid & 1) << 4;
    int br  = tid >> 3;
    int bc  = (tid & 7) << 2;
    int wrp = tid >> 5, ln = tid & 31;
    int ty  = ((wrp >> 1) << 2) | (ln >> 3);
    int tx  = ((wrp & 1) << 3) | (ln & 7);
    int ry  = ty << 3;
    int rxc = tx << 2;

    u64t acc2[8][2];
    #pragma unroll
    for (int i = 0; i < 8; i++) { acc2[i][0] = 0ull; acc2[i][1] = 0ull; }

    for (int k0 = kb; k0 < ke; k0 += 32) {
        float4 a[4];
        #pragma unroll
        for (int c = 0; c < 4; c++)
            a[c] = *(const float4*)(A + (size_t)(m0 + ar) * K + k0 + ac + (c << 2));
        float4 b0 = *(const float4*)(B + (size_t)(k0 + br) * 64 + bc);
        float4 b1 = *(const float4*)(B + (size_t)(k0 + br) * 64 + bc + 32);
        __syncthreads();
        #pragma unroll
        for (int c = 0; c < 4; c++) {
            As[ac + (c << 2) + 0][ar] = a[c].x;
            As[ac + (c << 2) + 1][ar] = a[c].y;
            As[ac + (c << 2) + 2][ar] = a[c].z;
            As[ac + (c << 2) + 3][ar] = a[c].w;
        }
        *(float4*)&Bs[br][bc]      = b0;
        *(float4*)&Bs[br][bc + 32] = b1;
        __syncthreads();
        #pragma unroll
        for (int k = 0; k < 32; k++) {
            float4 av0 = *(const float4*)&As[k][ry];
            float4 av1 = *(const float4*)&As[k][ry + 4];
            float4 bv  = *(const float4*)&Bs[k][rxc];
            u64t bp0 = ((const u64t*)&bv)[0], bp1 = ((const u64t*)&bv)[1];
            float aa[8] = {av0.x, av0.y, av0.z, av0.w, av1.x, av1.y, av1.z, av1.w};
            #pragma unroll
            for (int i = 0; i < 8; i++) {
                u64t ai = bcast2(aa[i]);
                fma2(acc2[i][0], ai, bp0);
                fma2(acc2[i][1], ai, bp1);
            }
        }
    }
    int r = m0 + ry;
    #pragma unroll
    for (int i = 0; i < 8; i++) {
        float2 v0 = unpack2(acc2[i][0]);
        float2 v1 = unpack2(acc2[i][1]);
        float4 v = make_float4(v0.x, v0.y, v1.x, v1.y);
        *(float4*)(part + (size_t)s * M * 64 + (size_t)(r + i) * 64 + rxc) = v;
    }
}

__global__ void splitk_reduce_kernel(const float* __restrict__ part, const float* __restrict__ bias,
                                     float* __restrict__ C, int M, int S, int relu)
{
    int idx = blockIdx.x * 256 + threadIdx.x;
    if (idx >= M * 64) return;
    float s = 0.f;
    for (int p = 0; p < S; p++) s += part[(size_t)p * M * 64 + idx];
    if (bias) s += bias[idx & 63];
    if (relu) s = fmaxf(s, 0.f);
    C[idx] = s;
}

__global__ void cs_reduce_kernel(const float* __restrict__ CSP, float* __restrict__ CS)
{
    int m = blockIdx.y;
    int j = blockIdx.x * 256 + threadIdx.x;
    float s = 0.f;
    #pragma unroll
    for (int p = 0; p < 32; p++) s += CSP[((size_t)m * 32 + p) * NT + j];
    CS[m * NT + j] = s;
}

__global__ void coefs_kernel(const float* __restrict__ sgw, const float* __restrict__ ffw,
                             const float* __restrict__ f4w,
                             const float* __restrict__ cs, float* __restrict__ coef)
{
    int j = blockIdx.x * 256 + threadIdx.x;
    float m2 = fmaxf(sgw[0], sgw[1]);
    float e0 = expf(sgw[0] - m2), e1 = expf(sgw[1] - m2);
    float sa0 = e0 / (e0 + e1), sa1 = e1 / (e0 + e1);
    float mf = fmaxf(ffw[0], ffw[1]);
    float f0 = expf(ffw[0] - mf), f1 = expf(ffw[1] - mf);
    float fa0 = f0 / (f0 + f1), fa1 = f1 / (f0 + f1);
    float m4 = fmaxf(fmaxf(f4w[0], f4w[1]), fmaxf(f4w[2], f4w[3]));
    float w0 = expf(f4w[0] - m4), w1 = expf(f4w[1] - m4), w2 = expf(f4w[2] - m4), w3 = expf(f4w[3] - m4);
    float ws = w0 + w1 + w2 + w3;
    w0 /= ws; w1 /= ws; w2 /= ws; w3 /= ws;

    float csv[7];
    #pragma unroll
    for (int m = 0; m < 7; m++) csv[m] = cs[m * NT + j];
    float uP  = (csv[1] > 0.05f) ? 1.f : 0.f;
    float uQ  = (csv[2] > 0.05f) ? 1.f : 0.f;
    float uFA = (csv[3] > 0.05f) ? 1.f : 0.f;
    float uFS = (csv[4] > 0.05f) ? 1.f : 0.f;
    float uSA = (csv[5] > 0.05f) ? 1.f : 0.f;
    float uSS = (csv[6] > 0.05f) ? 1.f : 0.f;
    float dSem = fmaxf(sa0 * uP  + sa1 * uQ,  1e-12f);
    float dFp  = fmaxf(fa0 * uFA + fa1 * uFS, 1e-12f);
    float dSt  = fmaxf(fa0 * uSA + fa1 * uSS, 1e-12f);

    coef[0 * NT + j] = w0 / fmaxf(csv[0], 1e-12f);
    coef[1 * NT + j] = w1 * sa0 / (fmaxf(csv[1], 1e-12f) * dSem);
    coef[2 * NT + j] = w1 * sa1 / (fmaxf(csv[2], 1e-12f) * dSem);
    coef[3 * NT + j] = w2 * fa0 / (fmaxf(csv[3], 1e-12f) * dFp);
    coef[4 * NT + j] = w2 * fa1 / (fmaxf(csv[4], 1e-12f) * dFp);
    coef[5 * NT + j] = w3 * fa0 / (fmaxf(csv[5], 1e-12f) * dSt);
    coef[6 * NT + j] = w3 * fa1 / (fmaxf(csv[6], 1e-12f) * dSt);
}

// Triangular symmetric combine (see round-12 derivation).
__global__ void __launch_bounds__(256)
combine_tri_kernel(const float* __restrict__ G,  const float* __restrict__ P,
                   const float* __restrict__ Q,  const float* __restrict__ FA,
                   const float* __restrict__ FS, const float* __restrict__ SA,
                   const float* __restrict__ SS, const float* __restrict__ coef,
                   float* __restrict__ out, float* __restrict__ part)
{
    const int nb = 64;
    int idx = blockIdx.x;
    float nb2 = nb + 0.5f;
    int bi = (int)(nb2 - sqrtf(fmaxf(nb2 * nb2 - 2.0f * idx, 0.f)));
    if (bi < 0) bi = 0;
    if (bi > nb - 1) bi = nb - 1;
    while (bi > 0 && (bi * nb - (bi * (bi - 1)) / 2) > idx) bi--;
    while (((bi + 1) * nb - ((bi + 1) * bi) / 2) <= idx) bi++;
    int bj = bi + (idx - (bi * nb - (bi * (bi - 1)) / 2));

    __shared__ float S[64][65];
    int row = threadIdx.x >> 2;
    int cc  = (threadIdx.x & 3) << 4;
    int gi  = bi * 64 + row;
    int gj  = bj * 64 + cc;

    float cfi[7];
    #pragma unroll
    for (int m = 0; m < 7; m++) cfi[m] = coef[m * NT + gi];

    float rsum = 0.f;
    #pragma unroll
    for (int c4 = 0; c4 < 16; c4 += 4) {
        size_t e = (size_t)gi * NT + gj + c4;
        float4 r = make_float4(0.f, 0.f, 0.f, 0.f);
#define ACC(buf, m) { float4 v = *(const float4*)((buf) + e);                     \
                      float4 k = *(const float4*)(coef + (m) * NT + gj + c4);     \
                      r.x = fmaf(k.x + cfi[m], v.x, r.x);                         \
                      r.y = fmaf(k.y + cfi[m], v.y, r.y);                         \
                      r.z = fmaf(k.z + cfi[m], v.z, r.z);                         \
                      r.w = fmaf(k.w + cfi[m], v.w, r.w); }
        ACC(G, 0) ACC(P, 1) ACC(Q, 2) ACC(FA, 3) ACC(FS, 4) ACC(SA, 5) ACC(SS, 6)
#undef ACC
        *(float4*)(out + e) = r;
        S[row][cc + c4 + 0] = r.x;
        S[row][cc + c4 + 1] = r.y;
        S[row][cc + c4 + 2] = r.z;
        S[row][cc + c4 + 3] = r.w;
        rsum += r.x + r.y + r.z + r.w;
    }
    rsum += __shfl_xor_sync(0xffffffffu, rsum, 1);
    rsum += __shfl_xor_sync(0xffffffffu, rsum, 2);
    if ((threadIdx.x & 3) == 0)
        part[(size_t)bj * NT + gi] = rsum;

    if (bi != bj) {
        __syncthreads();
        float csum = 0.f;
        #pragma unroll
        for (int c4 = 0; c4 < 16; c4 += 4) {
            float4 v = make_float4(S[cc + c4 + 0][row], S[cc + c4 + 1][row],
                                   S[cc + c4 + 2][row], S[cc + c4 + 3][row]);
            *(float4*)(out + (size_t)(bj * 64 + row) * NT + bi * 64 + cc + c4) = v;
            csum += v.x + v.y + v.z + v.w;
        }
        csum += __shfl_xor_sync(0xffffffffu, csum, 1);
        csum += __shfl_xor_sync(0xffffffffu, csum, 2);
        if ((threadIdx.x & 3) == 0)
            part[(size_t)bi * NT + bj * 64 + row] = csum;
    }
}

__global__ void ct_reduce_kernel(const float* __restrict__ part, float* __restrict__ ct)
{
    int j = blockIdx.x * 256 + threadIdx.x;
    float s = 0.f;
    #pragma unroll
    for (int p = 0; p < 64; p++) s += part[(size_t)p * NT + j];
    ct[j] = s;
}

__global__ void scale_cols_kernel(float* __restrict__ A, const float* __restrict__ ct)
{
    size_t e = ((size_t)blockIdx.x * 256 + threadIdx.x) << 2;
    int j = (int)(e & (NT - 1));
    float4 v = *(float4*)(A + e);
    float4 c = *(const float4*)(ct + j);
    v.x /= fmaxf(c.x, 1e-12f); v.y /= fmaxf(c.y, 1e-12f);
    v.z /= fmaxf(c.z, 1e-12f); v.w /= fmaxf(c.w, 1e-12f);
    *(float4*)(A + e) = v;
}

__global__ void x1w2_kernel(const float* __restrict__ X1, const float* __restrict__ W2,
                            float* __restrict__ H2)
{
    int i = blockIdx.x * 256 + threadIdx.x;
    if (i >= NT) return;
    float s0 = 0.f, s1 = 0.f, s2 = 0.f;
    #pragma unroll 8
    for (int k = 0; k < COM; k++) {
        float x = X1[(size_t)i * COM + k];
        s0 = fmaf(x, W2[k * 3 + 0], s0);
        s1 = fmaf(x, W2[k * 3 + 1], s1);
        s2 = fmaf(x, W2[k * 3 + 2], s2);
    }
    H2[i * 3 + 0] = s0; H2[i * 3 + 1] = s1; H2[i * 3 + 2] = s2;
}

__global__ void logits_kernel(const float* __restrict__ A, const float* __restrict__ H2,
                              const float* __restrict__ b2, float* __restrict__ out)
{
    int i = blockIdx.x, tid = threadIdx.x;
    const float* row = A + (size_t)i * NT;
    float s0 = 0.f, s1 = 0.f, s2 = 0.f;
    for (int k = tid; k < NT; k += 256) {
        float a = row[k];
        s0 = fmaf(a, H2[k * 3 + 0], s0);
        s1 = fmaf(a, H2[k * 3 + 1], s1);
        s2 = fmaf(a, H2[k * 3 + 2], s2);
    }
    #pragma unroll
    for (int o = 16; o; o >>= 1) {
        s0 += __shfl_xor_sync(0xffffffffu, s0, o);
        s1 += __shfl_xor_sync(0xffffffffu, s1, o);
        s2 += __shfl_xor_sync(0xffffffffu, s2, o);
    }
    __shared__ float sh[3][8];
    int w = tid >> 5, l = tid & 31;
    if (l == 0) { sh[0][w] = s0; sh[1][w] = s1; sh[2][w] = s2; }
    __syncthreads();
    if (tid == 0) {
        float x0 = 0.f, x1 = 0.f, x2 = 0.f;
        #pragma unroll
        for (int t = 0; t < 8; t++) { x0 += sh[0][t]; x1 += sh[1][t]; x2 += sh[2][t]; }
        x0 += b2[0]; x1 += b2[1]; x2 += b2[2];
        float m  = fmaxf(x0, fmaxf(x1, x2));
        float ls = logf(expf(x0 - m) + expf(x1 - m) + expf(x2 - m));
        out[i * 3 + 0] = x0 - m - ls;
        out[i * 3 + 1] = x1 - m - ls;
        out[i * 3 + 2] = x2 - m - ls;
    }
}

// ---------------- host orchestration (single stream) -------------------------

extern "C" void kernel_launch(void* const* d_in, const int* in_sizes, int n_in,
                              void* d_out, int out_size)
{
    const float* features  = (const float*)d_in[0];
    const float* adj_ori   = (const float*)d_in[1];
    const float* mp_pap    = (const float*)d_in[2];
    const float* mp_psp    = (const float*)d_in[3];
    const float* fgo_w     = (const float*)d_in[6];
    const float* fpo_w     = (const float*)d_in[7];
    const float* sgg_pap_w = (const float*)d_in[8];
    const float* sgg_psp_w = (const float*)d_in[9];
    const float* sg_agg_w  = (const float*)d_in[10];
    const float* f_agg_f_w = (const float*)d_in[11];
    const float* f_agg_w   = (const float*)d_in[12];
    const float* topo_W_a  = (const float*)d_in[13];
    const float* topo_b_a  = (const float*)d_in[14];
    const float* topo_W_s  = (const float*)d_in[15];
    const float* topo_b_s  = (const float*)d_in[16];
    const float* fgt_w_a   = (const float*)d_in[17];
    const float* fgt_w_s   = (const float*)d_in[18];
    const float* gcn_W1    = (const float*)d_in[19];
    const float* gcn_b1    = (const float*)d_in[20];
    const float* gcn_W2    = (const float*)d_in[21];
    const float* gcn_b2    = (const float*)d_in[22];
    (void)in_sizes; (void)n_in; (void)out_size;

    float* out   = (float*)d_out;
    float* NAdj  = out + (size_t)NT * NCLS;

    float* big = nullptr; float* sm = nullptr; int* ib = nullptr;
    __nv_bfloat16* b1p = nullptr; __nv_bfloat16* b2p = nullptr; __nv_bfloat16* b3p = nullptr;
    cudaGetSymbolAddress((void**)&big, g_big);
    cudaGetSymbolAddress((void**)&sm,  g_small);
    cudaGetSymbolAddress((void**)&ib,  g_ibuf);
    cudaGetSymbolAddress((void**)&b1p, g_bf1);
    cudaGetSymbolAddress((void**)&b2p, g_bf2);
    cudaGetSymbolAddress((void**)&b3p, g_bf3);

    float* G   = big + 0ll * NT * NT;
    float* P   = big + 1ll * NT * NT;
    float* Q   = big + 2ll * NT * NT;
    float* FAb = big + 3ll * NT * NT;
    float* FSb = big + 4ll * NT * NT;
    float* SAb = big + 5ll * NT * NT;   // sim_r_A (full), then s_h_A (triangular)
    float* SSb = big + 6ll * NT * NT;

    float* SIMS  = sm + OFF_SIMS;
    float* FPA   = sm + OFF_FPA;
    float* FPS   = sm + OFF_FPS;
    float* THA   = sm + OFF_THA;
    float* THS   = sm + OFF_THS;
    float* SWA   = sm + OFF_SWA;
    float* SWS   = sm + OFF_SWS;
    float* H0    = sm + OFF_H0;
    float* X1    = sm + OFF_X1;
    float* H2    = sm + OFF_H2;
    float* CS    = sm + OFF_CS;
    float* COEF  = sm + OFF_COEF;
    float* CT    = sm + OFF_CT;
    float* PART2 = sm + OFF_PART2;
    float* CSP   = sm + OFF_CSP;
    float* SPART = sm + OFF_SPART;

    int* IDXA = ib + OFF_IDXA; int* CNTA = ib + OFF_CNTA;
    int* IDXS = ib + OFF_IDXS; int* CNTS = ib + OFF_CNTS;

    const size_t BUF = (size_t)NT * 256;
    const int TRI32 = 32 * 33 / 2;   // 528
    const int TRI64 = 64 * 65 / 2;   // 2080

    // ---- adjacency index lists + feature propagation (independent of sims) ----
    build_idx_kernel<<<NT, 128>>>(adj_ori, NT, NAr, IDXA, CNTA);
    build_idx_kernel<<<NT, 128>>>(adj_ori, NT + NAr, NSr, IDXS, CNTS);
    gather_sum_kernel<<<dim3(1, NT), 32>>>(features + (size_t)NT * FEAT, FEAT, IDXA, CNTA, FPA, FEAT);
    gather_sum_kernel<<<dim3(1, NT), 32>>>(features + (size_t)(NT + NAr) * FEAT, FEAT, IDXS, CNTS, FPS, FEAT);

    // ---- prep batch A: 7 jobs ----
    {
        PrepJobs pj;
        pj.j[0] = {features,                              fgo_w,     b1p + 0*BUF, b2p + 0*BUF, b3p + 0*BUF, NT,  FEAT};
        pj.j[1] = {features + (size_t)NT * FEAT,          fgo_w,     b1p + 1*BUF, b2p + 1*BUF, b3p + 1*BUF, NAr, FEAT};
        pj.j[2] = {mp_pap,                                sgg_pap_w, b1p + 2*BUF, b2p + 2*BUF, b3p + 2*BUF, NT,  MPD};
        pj.j[3] = {mp_psp,                                sgg_psp_w, b1p + 3*BUF, b2p + 3*BUF, b3p + 3*BUF, NT,  MPD};
        pj.j[4] = {features + (size_t)(NT + NAr) * FEAT,  fgo_w,     b1p + 4*BUF, b2p + 4*BUF, b3p + 4*BUF, NSr, FEAT};
        pj.j[5] = {FPA,                                   fpo_w,     b1p + 5*BUF, b2p + 5*BUF, b3p + 5*BUF, NT,  FEAT};
        pj.j[6] = {FPS,                                   fpo_w,     b1p + 6*BUF, b2p + 6*BUF, b3p + 6*BUF, NT,  FEAT};
        prep_norm_multi_kernel<<<dim3(NT / 4, 7), 128>>>(pj);
    }

    // ---- sim batch 1 (tensor cores): G, sim_r_A, P, Q, sim_r_S, f_h_A, f_h_S ----
    {
        SimJobs sj;
        sj.j[0] = {b1p + 0*BUF, b2p + 0*BUF, b3p + 0*BUF, G,    CSP + 0ll * 32 * NT, NT,  256, 32, 0.1f, 0};
        sj.j[1] = {b1p + 1*BUF, b2p + 1*BUF, b3p + 1*BUF, SAb,  nullptr,             NT,  256, 32, 0.1f, 1};
        sj.j[2] = {b1p + 2*BUF, b2p + 2*BUF, b3p + 2*BUF, P,    CSP + 1ll * 32 * NT, NT,  128, 32, 0.1f, 0};
        sj.j[3] = {b1p + 3*BUF, b2p + 3*BUF, b3p + 3*BUF, Q,    CSP + 2ll * 32 * NT, NT,  128, 32, 0.1f, 0};
        sj.j[4] = {b1p + 4*BUF, b2p + 4*BUF, b3p + 4*BUF, SIMS, nullptr,             NSr, 256, 8,  0.1f, 1};
        sj.j[5] = {b1p + 5*BUF, b2p + 5*BUF, b3p + 5*BUF, FAb,  CSP + 3ll * 32 * NT, NT,  256, 32, 0.2f, 0};
        sj.j[6] = {b1p + 6*BUF, b2p + 6*BUF, b3p + 6*BUF, FSb,  CSP + 4ll * 32 * NT, NT,  256, 32, 0.2f, 0};
        simgemm_tc_multi_kernel<<<dim3(TRI32, 7), 256>>>(sj);
    }

    // ---- topo chains (A then S) ----
    gemm128_splitk_kernel<<<dim3(NT / 128, 8), 256>>>(SAb, topo_W_a, SPART, NT, NAr, NAr / 8);
    splitk_reduce_kernel<<<(NT * 64) / 256, 256>>>(SPART, nullptr, SWA, NT, 8, 0);
    gather64b_kernel<<<NT, 64>>>(SWA, IDXA, CNTA, topo_b_a, THA);
    gemm128_splitk_kernel<<<dim3(NSr / 128, 8), 256>>>(SIMS, topo_W_s, SPART, NSr, NSr, NSr / 8);
    splitk_reduce_kernel<<<(NSr * 64) / 256, 256>>>(SPART, nullptr, SWS, NSr, 8, 0);
    gather64b_kernel<<<NT, 64>>>(SWS, IDXS, CNTS, topo_b_s, THS);

    // ---- prep batch B: 2 jobs ----
    {
        PrepJobs pj;
        pj.j[0] = {THA, fgt_w_a, b1p + 2*BUF, b2p + 2*BUF, b3p + 2*BUF, NT, COM};
        pj.j[1] = {THS, fgt_w_s, b1p + 3*BUF, b2p + 3*BUF, b3p + 3*BUF, NT, COM};
        for (int t = 2; t < 7; t++) pj.j[t] = {THA, fgt_w_a, b1p + 2*BUF, b2p + 2*BUF, b3p + 2*BUF, 0, COM};
        prep_norm_multi_kernel<<<dim3(NT / 4, 2), 128>>>(pj);
    }

    // ---- sim batch 2: s_h_A, s_h_S (triangular-only stores) ----
    {
        SimJobs sj;
        sj.j[0] = {b1p + 2*BUF, b2p + 2*BUF, b3p + 2*BUF, SAb, CSP + 5ll * 32 * NT, NT, 128, 32, 0.1f, 0};
        sj.j[1] = {b1p + 3*BUF, b2p + 3*BUF, b3p + 3*BUF, SSb, CSP + 6ll * 32 * NT, NT, 128, 32, 0.1f, 0};
        for (int t = 2; t < 7; t++) sj.j[t] = {b1p + 2*BUF, b2p + 2*BUF, b3p + 2*BUF, nullptr, nullptr, 0, 16, 0, 0.1f, 0};
        simgemm_tc_multi_kernel<<<dim3(TRI32, 2), 256>>>(sj);
    }

    // ---- GCN first half (independent) ----
    gemm_n64_kernel<<<NT / 64, 256>>>(features, gcn_W1, nullptr, H0, NT, FEAT, 0);

    // ---- fused channel attention (triangular symmetric combine) ----
    cs_reduce_kernel<<<dim3(NT / 256, 7), 256>>>(CSP, CS);
    coefs_kernel<<<NT / 256, 256>>>(sg_agg_w, f_agg_f_w, f_agg_w, CS, COEF);
    combine_tri_kernel<<<TRI64, 256>>>(G, P, Q, FAb, FSb, SAb, SSb, COEF, NAdj, PART2);
    ct_reduce_kernel<<<NT / 256, 256>>>(PART2, CT);
    scale_cols_kernel<<<(NT * NT) / 1024, 256>>>(NAdj, CT);

    // ---- GCN second half ----
    gemm128_splitk_kernel<<<dim3(NT / 128, 8), 256>>>(NAdj, H0, SPART, NT, NT, NT / 8);
    splitk_reduce_kernel<<<(NT * 64) / 256, 256>>>(SPART, gcn_b1, X1, NT, 8, 1);
    x1w2_kernel<<<NT / 256, 256>>>(X1, gcn_W2, H2);
    logits_kernel<<<NT, 256>>>(NAdj, H2, gcn_b2, out);
}

// round 16
// speedup vs baseline: 1.0627x; 1.0627x over previous
#include <cuda_runtime.h>
#include <cuda_bf16.h>
#include <math.h>

#define NT   4096
#define NAr  4096
#define NSr  1024
#define NALL 9216
#define FEAT 128
#define COM  64
#define MPD  64
#define NCLS 3
#define CAP  128   // max nnz per adjacency row (expected ~20, p=0.005)

// ---------------- static device scratch (no allocations allowed) -------------
__device__ float g_big[7ll * NT * NT];

// bf16 3-way split feature buffers for tensor-core sims (7 jobs, K<=256)
__device__ __nv_bfloat16 g_bf1[7ll * NT * 256];
__device__ __nv_bfloat16 g_bf2[7ll * NT * 256];
__device__ __nv_bfloat16 g_bf3[7ll * NT * 256];

#define OFF_SIMS  0                         // 1024*1024
#define OFF_FPA   (OFF_SIMS + NSr*NSr)      // 4096*128
#define OFF_FPS   (OFF_FPA  + NT*FEAT)      // 4096*128
#define OFF_THA   (OFF_FPS  + NT*FEAT)      // 4096*64
#define OFF_THS   (OFF_THA  + NT*COM)       // 4096*64
#define OFF_SWA   (OFF_THS  + NT*COM)       // 4096*64
#define OFF_SWS   (OFF_SWA  + NT*COM)       // 1024*64
#define OFF_H0    (OFF_SWS  + NSr*COM)      // 4096*64
#define OFF_X1    (OFF_H0   + NT*COM)       // 4096*64
#define OFF_H2    (OFF_X1   + NT*COM)       // 4096*3
#define OFF_CS    (OFF_H2   + NT*NCLS)      // 7*4096
#define OFF_COEF  (OFF_CS   + 7*NT)         // 7*4096
#define OFF_CT    (OFF_COEF + 7*NT)         // 4096
#define OFF_PART2 (OFF_CT   + NT)           // 64*4096 row partials
#define OFF_CSP   (OFF_PART2+ 64*NT)        // 7*32*4096
#define OFF_SPART (OFF_CSP  + 7*32*NT)      // 8*4096*64
#define SMALL_TOT (OFF_SPART + 8*NT*64)
__device__ float g_small[SMALL_TOT];

#define OFF_IDXA 0
#define OFF_CNTA (OFF_IDXA + NT*CAP)
#define OFF_IDXS (OFF_CNTA + NT)
#define OFF_CNTS (OFF_IDXS + NT*CAP)
#define IBUF_TOT (OFF_CNTS + NT)
__device__ int g_ibuf[IBUF_TOT];

// ---------------- packed f32x2 helpers ----------------
typedef unsigned long long u64t;

__device__ __forceinline__ u64t bcast2(float a)
{
    u64t r;
    asm("mov.b64 %0, {%1, %1};" : "=l"(r) : "r"(__float_as_uint(a)));
    return r;
}
__device__ __forceinline__ void fma2(u64t& acc, u64t a, u64t b)
{
    asm("fma.rn.f32x2 %0, %1, %2, %0;" : "+l"(acc) : "l"(a), "l"(b));
}
__device__ __forceinline__ float2 unpack2(u64t v)
{
    unsigned int lo, hi;
    asm("mov.b64 {%0, %1}, %2;" : "=r"(lo), "=r"(hi) : "l"(v));
    return make_float2(__uint_as_float(lo), __uint_as_float(hi));
}

// ---------------- tensor-core / async helpers ----------------
#define LDSM4(d, addr) \
    asm volatile("ldmatrix.sync.aligned.m8n8.x4.shared.b16 {%0,%1,%2,%3}, [%4];" \
                 : "=r"((d)[0]), "=r"((d)[1]), "=r"((d)[2]), "=r"((d)[3]) : "r"(addr))

#define MMA16816(c, a, b0, b1) \
    asm volatile("mma.sync.aligned.m16n8k16.row.col.f32.bf16.bf16.f32 " \
                 "{%0,%1,%2,%3},{%4,%5,%6,%7},{%8,%9},{%0,%1,%2,%3};" \
                 : "+f"((c)[0]), "+f"((c)[1]), "+f"((c)[2]), "+f"((c)[3]) \
                 : "r"((a)[0]), "r"((a)[1]), "r"((a)[2]), "r"((a)[3]), "r"(b0), "r"(b1))

__device__ __forceinline__ void cp16(unsigned int dst, const void* src)
{
    asm volatile("cp.async.cg.shared.global [%0], [%1], 16;" :: "r"(dst), "l"(src));
}
__device__ __forceinline__ void cp_commit() { asm volatile("cp.async.commit_group;"); }
__device__ __forceinline__ void cp_wait0()  { asm volatile("cp.async.wait_group 0;" ::: "memory"); }
__device__ __forceinline__ void cp_wait1()  { asm volatile("cp.async.wait_group 1;" ::: "memory"); }

// ---------------- job structs (passed by value as kernel args) ---------------
struct PrepJob { const float* src; const float* w;
                 __nv_bfloat16* d1; __nv_bfloat16* d2; __nv_bfloat16* d3; int N; int D; };
struct PrepJobs { PrepJob j[7]; };
struct SimJob  { const __nv_bfloat16* X1; const __nv_bfloat16* X2; const __nv_bfloat16* X3;
                 float* C; float* cs; int N; int K; int nBlk; float th; int mirror; };
struct SimJobs { SimJob j[7]; };

// ---------------- kernels ----------------------------------------------------

// Multi-job per-head weighted + L2-row-normalized features as a 3-way bf16
// split: v = d1 + d2 + d3 with residual <= 2^-27 |v|. Uses division (matching
// the reference's elementwise x / norm). Layout [N][2*D].
__global__ void prep_norm_multi_kernel(PrepJobs jobs)
{
    PrepJob jb = jobs.j[blockIdx.y];
    int row  = blockIdx.x * (blockDim.x >> 5) + (threadIdx.x >> 5);
    int lane = threadIdx.x & 31;
    if (row >= jb.N) return;
    const float* src = jb.src;
    const float* w   = jb.w;
    int D = jb.D;
    int HD = 2 * D;
    for (int h = 0; h < 2; h++) {
        float ss = 0.f;
        for (int d = lane; d < D; d += 32) {
            float v = src[(size_t)row * D + d] * w[h * D + d];
            ss += v * v;
        }
        #pragma unroll
        for (int o = 16; o; o >>= 1) ss += __shfl_xor_sync(0xffffffffu, ss, o);
        float nrm = fmaxf(sqrtf(ss), 1e-12f);
        for (int d = lane; d < D; d += 32) {
            float v = (src[(size_t)row * D + d] * w[h * D + d]) / nrm;
            __nv_bfloat16 h1 = __float2bfloat16(v);
            float v1 = v - __bfloat162float(h1);
            __nv_bfloat16 h2 = __float2bfloat16(v1);
            float v2 = v1 - __bfloat162float(h2);
            __nv_bfloat16 h3 = __float2bfloat16(v2);
            size_t e = (size_t)row * HD + h * D + d;
            jb.d1[e] = h1;
            jb.d2[e] = h2;
            jb.d3[e] = h3;
        }
    }
}

__device__ __forceinline__ float thrf(float v, float scale, float th)
{
    v *= scale;
    return (v < th) ? 0.f : v;
}

// Multi-job C = threshold(0.5 * X @ X^T) via 3-way bf16 tensor-core MMA with
// SPLIT ACCUMULATORS (numerics identical to the round-15 passing kernel) and
// cp.async DOUBLE BUFFERING: chunk s+1's global loads overlap chunk s's MMAs.
// Dynamic smem: 2 stages x 6 planes x [128][24] bf16 = 73728 B.
#define PLN  6144           // one plane: 128 rows * 24 bf16 * 2B
#define STG  (6 * PLN)      // one stage: 6 planes
__global__ void __launch_bounds__(256, 1)
simgemm_tc_multi_kernel(SimJobs jobs)
{
    extern __shared__ __align__(16) char dsm[];
    SimJob jb = jobs.j[blockIdx.y];
    const int nBlk = jb.nBlk;
    int idx = blockIdx.x;
    if (idx >= nBlk * (nBlk + 1) / 2) return;

    float nb2 = nBlk + 0.5f;
    int by = (int)(nb2 - sqrtf(fmaxf(nb2 * nb2 - 2.0f * idx, 0.f)));
    if (by < 0) by = 0;
    if (by > nBlk - 1) by = nBlk - 1;
    while (by > 0 && (by * nBlk - (by * (by - 1)) / 2) > idx) by--;
    while (((by + 1) * nBlk - ((by + 1) * by) / 2) <= idx) by++;
    int bx = by + (idx - (by * nBlk - (by * (by - 1)) / 2));

    const int m0 = by * 128, n0 = bx * 128;
    const int N = jb.N, K = jb.K;

    const int tid = threadIdx.x;
    const int wrp = tid >> 5, ln = tid & 31;
    const int wm = wrp & 3, wn = wrp >> 2;   // 4 x 2 warp grid

    float accM[2][8][4], accC[2][8][4];
    #pragma unroll
    for (int mi = 0; mi < 2; mi++)
        #pragma unroll
        for (int ni = 0; ni < 8; ni++)
            #pragma unroll
            for (int t = 0; t < 4; t++) { accM[mi][ni][t] = 0.f; accC[mi][ni][t] = 0.f; }

    const int lrow = ln & 15;
    const int lk8  = (ln >> 4) << 3;
    const int lrw  = tid >> 1;           // 0..127 loader row
    const int lq   = (tid & 1) << 3;     // 0 or 8 (bf16 elements)

    const unsigned sbase = (unsigned)__cvta_generic_to_shared(dsm);
    const unsigned doff  = (unsigned)(lrw * 48 + lq * 2);   // bytes within a plane

#define ISSUE(stage, k0) {                                                      \
    size_t ea = (size_t)(m0 + lrw) * K + (k0) + lq;                             \
    size_t eb = (size_t)(n0 + lrw) * K + (k0) + lq;                             \
    unsigned sb = sbase + (stage) * STG + doff;                                 \
    cp16(sb + 0 * PLN, jb.X1 + ea);                                             \
    cp16(sb + 1 * PLN, jb.X2 + ea);                                             \
    cp16(sb + 2 * PLN, jb.X3 + ea);                                             \
    cp16(sb + 3 * PLN, jb.X1 + eb);                                             \
    cp16(sb + 4 * PLN, jb.X2 + eb);                                             \
    cp16(sb + 5 * PLN, jb.X3 + eb);                                             \
    cp_commit(); }

    const int S = K >> 4;
    ISSUE(0, 0);
    int buf = 0;
    for (int s = 0; s < S; s++) {
        if (s + 1 < S) ISSUE(buf ^ 1, (s + 1) << 4);
        if (s + 1 < S) cp_wait1(); else cp_wait0();
        __syncthreads();

        const unsigned stg = sbase + buf * STG;
        unsigned int a1[2][4], a2[2][4], a3[2][4];
        #pragma unroll
        for (int mi = 0; mi < 2; mi++) {
            unsigned ao = stg + (unsigned)((wm * 32 + mi * 16 + lrow) * 48 + lk8 * 2);
            LDSM4(a1[mi], ao + 0 * PLN);
            LDSM4(a2[mi], ao + 1 * PLN);
            LDSM4(a3[mi], ao + 2 * PLN);
        }
        #pragma unroll
        for (int np = 0; np < 4; np++) {
            unsigned int b1[4], b2[4], b3[4];
            unsigned bo = stg + (unsigned)((wn * 64 + np * 16 + lrow) * 48 + lk8 * 2);
            LDSM4(b1, bo + 3 * PLN);
            LDSM4(b2, bo + 4 * PLN);
            LDSM4(b3, bo + 5 * PLN);
            #pragma unroll
            for (int bi = 0; bi < 2; bi++) {
                unsigned int b1a = bi ? b1[1] : b1[0], b1b = bi ? b1[3] : b1[2];
                unsigned int b2a = bi ? b2[1] : b2[0], b2b = bi ? b2[3] : b2[2];
                unsigned int b3a = bi ? b3[1] : b3[0], b3b = bi ? b3[3] : b3[2];
                int ni = np * 2 + bi;
                #pragma unroll
                for (int mi = 0; mi < 2; mi++) {
                    MMA16816(accM[mi][ni], a1[mi], b1a, b1b);   // h1*h1 (main)
                    MMA16816(accC[mi][ni], a1[mi], b2a, b2b);   // h1*h2
                    MMA16816(accC[mi][ni], a2[mi], b1a, b1b);   // h2*h1
                    MMA16816(accC[mi][ni], a2[mi], b2a, b2b);   // h2*h2
                    MMA16816(accC[mi][ni], a1[mi], b3a, b3b);   // h1*h3
                    MMA16816(accC[mi][ni], a3[mi], b1a, b1b);   // h3*h1
                }
            }
        }
        __syncthreads();
        buf ^= 1;
    }
#undef ISSUE

    // combine planes + threshold (identical to round 15)
    const float th = jb.th;
    float acc[2][8][4];
    #pragma unroll
    for (int mi = 0; mi < 2; mi++)
        #pragma unroll
        for (int ni = 0; ni < 8; ni++)
            #pragma unroll
            for (int t = 0; t < 4; t++)
                acc[mi][ni][t] = thrf(accM[mi][ni][t] + accC[mi][ni][t], 0.5f, th);

    float* C = jb.C;
    const int r  = ln >> 2;
    const int cp = (ln & 3) << 1;

    // direct stores
    #pragma unroll
    for (int mi = 0; mi < 2; mi++) {
        int g = m0 + wm * 32 + mi * 16 + r;
        #pragma unroll
        for (int ni = 0; ni < 8; ni++) {
            int gc = n0 + wn * 64 + ni * 8 + cp;
            *(float2*)&C[(size_t)g * N + gc]       = make_float2(acc[mi][ni][0], acc[mi][ni][1]);
            *(float2*)&C[(size_t)(g + 8) * N + gc] = make_float2(acc[mi][ni][2], acc[mi][ni][3]);
        }
    }
    if (bx > by && jb.mirror) {
        #pragma unroll
        for (int mi = 0; mi < 2; mi++) {
            int g = m0 + wm * 32 + mi * 16 + r;
            #pragma unroll
            for (int ni = 0; ni < 8; ni++) {
                int gc = n0 + wn * 64 + ni * 8 + cp;
                C[(size_t)gc * N + g]           = acc[mi][ni][0];
                C[(size_t)(gc + 1) * N + g]     = acc[mi][ni][1];
                C[(size_t)gc * N + g + 8]       = acc[mi][ni][2];
                C[(size_t)(gc + 1) * N + g + 8] = acc[mi][ni][3];
            }
        }
    }

    if (jb.cs) {
        __syncthreads();
        float* red = (float*)dsm;   // reuse smem: 768 floats
        #pragma unroll
        for (int ni = 0; ni < 8; ni++) {
            float s0 = acc[0][ni][0] + acc[0][ni][2] + acc[1][ni][0] + acc[1][ni][2];
            float s1 = acc[0][ni][1] + acc[0][ni][3] + acc[1][ni][1] + acc[1][ni][3];
            s0 += __shfl_xor_sync(0xffffffffu, s0, 4);
            s0 += __shfl_xor_sync(0xffffffffu, s0, 8);
            s0 += __shfl_xor_sync(0xffffffffu, s0, 16);
            s1 += __shfl_xor_sync(0xffffffffu, s1, 4);
            s1 += __shfl_xor_sync(0xffffffffu, s1, 8);
            s1 += __shfl_xor_sync(0xffffffffu, s1, 16);
            if (ln < 4) {
                red[wm * 128 + wn * 64 + ni * 8 + cp]     = s0;
                red[wm * 128 + wn * 64 + ni * 8 + cp + 1] = s1;
            }
        }
        #pragma unroll
        for (int mi = 0; mi < 2; mi++) {
            float r0 = 0.f, r1 = 0.f;
            #pragma unroll
            for (int ni = 0; ni < 8; ni++) {
                r0 += acc[mi][ni][0] + acc[mi][ni][1];
                r1 += acc[mi][ni][2] + acc[mi][ni][3];
            }
            r0 += __shfl_xor_sync(0xffffffffu, r0, 1);
            r0 += __shfl_xor_sync(0xffffffffu, r0, 2);
            r1 += __shfl_xor_sync(0xffffffffu, r1, 1);
            r1 += __shfl_xor_sync(0xffffffffu, r1, 2);
            if ((ln & 3) == 0) {
                red[512 + wn * 128 + wm * 32 + mi * 16 + r]     = r0;
                red[512 + wn * 128 + wm * 32 + mi * 16 + r + 8] = r1;
            }
        }
        __syncthreads();
        if (tid < 128) {
            float s = red[tid] + red[128 + tid] + red[256 + tid] + red[384 + tid];
            jb.cs[(size_t)by * N + n0 + tid] = s;
        }
        if (bx > by && tid >= 128 && tid < 256) {
            int rr = tid - 128;
            jb.cs[(size_t)bx * N + m0 + rr] = red[512 + rr] + red[640 + rr];
        }
    }
}

// Deterministic ballot-compacted nonzero index list; 4 warps scan disjoint
// segments, merged in segment order.
__global__ void build_idx_kernel(const float* __restrict__ adj, int col_off, int NR,
                                 int* __restrict__ idx, int* __restrict__ cnt)
{
    __shared__ int sidx[4][CAP];
    __shared__ int scnt[4];
    int i = blockIdx.x;
    const float* r = adj + (size_t)i * NALL + col_off;
    int w = threadIdx.x >> 5, lane = threadIdx.x & 31;
    int seg = NR >> 2;
    int b0  = w * seg;
    int count = 0;
    for (int base = b0; base < b0 + seg; base += 32) {
        float v = r[base + lane];
        unsigned m = __ballot_sync(0xffffffffu, v != 0.f);
        int pre = __popc(m & ((1u << lane) - 1u));
        if (v != 0.f && (count + pre) < CAP) sidx[w][count + pre] = base + lane;
        count += __popc(m);
    }
    if (lane == 0) scnt[w] = min(count, CAP);
    __syncthreads();
    int myoff = 0, tot = 0;
    #pragma unroll
    for (int p = 0; p < 4; p++) {
        if (p < w) myoff += scnt[p];
        tot += scnt[p];
    }
    for (int t = lane; t < scnt[w]; t += 32) {
        int pos = myoff + t;
        if (pos < CAP) idx[(size_t)i * CAP + pos] = sidx[w][t];
    }
    if (threadIdx.x == 0) cnt[i] = min(tot, CAP);
}

__global__ void gather_sum_kernel(const float* __restrict__ src, int lds,
                                  const int* __restrict__ idx, const int* __restrict__ cnt,
                                  float* __restrict__ out, int ldo)
{
    int i = blockIdx.y;
    int j = ((blockIdx.x * blockDim.x + threadIdx.x) << 2);
    int c = cnt[i];
    const int* ip = idx + (size_t)i * CAP;
    float4 s = make_float4(0.f, 0.f, 0.f, 0.f);
    for (int t = 0; t < c; t++) {
        float4 v = *(const float4*)(src + (size_t)ip[t] * lds + j);
        s.x += v.x; s.y += v.y; s.z += v.z; s.w += v.w;
    }
    *(float4*)(out + (size_t)i * ldo + j) = s;
}

__global__ void gather64b_kernel(const float* __restrict__ src,
                                 const int* __restrict__ idx, const int* __restrict__ cnt,
                                 const float* __restrict__ bias, float* __restrict__ out)
{
    int i = blockIdx.x;
    int c = threadIdx.x;
    int n = cnt[i];
    const int* ip = idx + (size_t)i * CAP;
    float s = 0.f;
    for (int t = 0; t < n; t++) s += src[(size_t)ip[t] * 64 + c];
    out[(size_t)i * 64 + c] = s + bias[c];
}

// C[M,64] = A[M,K] @ B[K,64] (+bias) (optional relu) — 64x64 tile, for small K
__global__ void __launch_bounds__(256)
gemm_n64_kernel(const float* __restrict__ A, const float* __restrict__ B,
                const float* __restrict__ bias, float* __restrict__ C,
                int M, int K, int relu)
{
    __shared__ float As[32][64];
    __shared__ float Bs[32][64];
    int tid = threadIdx.x;
    int m0  = blockIdx.x * 64;
    int ar  = tid >> 3;
    int ac  = (tid & 7) << 2;
    int br  = tid >> 4;
    int bc  = (tid & 15) << 2;
    int wrp = tid >> 5, ln = tid & 31;
    int ty  = ((wrp >> 1) << 2) | (ln >> 3);
    int tx  = ((wrp & 1) << 3) | (ln & 7);

    u64t acc2[4][2];
    #pragma unroll
    for (int i = 0; i < 4; i++) { acc2[i][0] = 0ull; acc2[i][1] = 0ull; }

    for (int k0 = 0; k0 < K; k0 += 32) {
        float4 a0 = *(const float4*)(A + (size_t)(m0 + ar)      * K + k0 + ac);
        float4 a1 = *(const float4*)(A + (size_t)(m0 + ar + 32) * K + k0 + ac);
        float4 b0 = *(const float4*)(B + (size_t)(k0 + br)      * 64 + bc);
        float4 b1 = *(const float4*)(B + (size_t)(k0 + br + 16) * 64 + bc);
        __syncthreads();
        As[ac+0][ar]    = a0.x; As[ac+1][ar]    = a0.y; As[ac+2][ar]    = a0.z; As[ac+3][ar]    = a0.w;
        As[ac+0][ar+32] = a1.x; As[ac+1][ar+32] = a1.y; As[ac+2][ar+32] = a1.z; As[ac+3][ar+32] = a1.w;
        *(float4*)&Bs[br][bc]      = b0;
        *(float4*)&Bs[br + 16][bc] = b1;
        __syncthreads();
        #pragma unroll
        for (int k = 0; k < 32; k++) {
            float4 av = *(const float4*)&As[k][ty << 2];
            float4 bv = *(const float4*)&Bs[k][tx << 2];
            u64t bp0 = ((const u64t*)&bv)[0], bp1 = ((const u64t*)&bv)[1];
            float a[4] = {av.x, av.y, av.z, av.w};
            #pragma unroll
            for (int i = 0; i < 4; i++) {
                u64t ai = bcast2(a[i]);
                fma2(acc2[i][0], ai, bp0);
                fma2(acc2[i][1], ai, bp1);
            }
        }
    }
    int r = m0 + (ty << 2), c = tx << 2;
    #pragma unroll
    for (int i = 0; i < 4; i++) {
        float2 v0 = unpack2(acc2[i][0]);
        float2 v1 = unpack2(acc2[i][1]);
        float vv[4] = {v0.x, v0.y, v1.x, v1.y};
        #pragma unroll
        for (int j = 0; j < 4; j++) {
            float v = vv[j] + (bias ? bias[c + j] : 0.f);
            if (relu) v = fmaxf(v, 0.f);
            C[(size_t)(r + i) * 64 + c + j] = v;
        }
    }
}

// split-K GEMM, 128x64 tile, 8x4 per thread. grid (M/128, S).
__global__ void __launch_bounds__(256)
gemm128_splitk_kernel(const float* __restrict__ A, const float* __restrict__ B,
                      float* __restrict__ part, int M, int K, int Kc)
{
    __shared__ float As[32][128];
    __shared__ float Bs[32][64];
    int tid = threadIdx.x;
    int m0  = blockIdx.x * 128;
    int s   = blockIdx.y;
    int kb  = s * Kc, ke = kb + Kc;
    int ar  = tid >> 1;
    int ac  = (tid & 1) << 4;
    int br  = tid >> 3;
    int bc  = (tid & 7) << 2;
    int wrp = tid >> 5, ln = tid & 31;
    int ty  = ((wrp >> 1) << 2) | (ln >> 3);
    int tx  = ((wrp & 1) << 3) | (ln & 7);
    int ry  = ty << 3;
    int rxc = tx << 2;

    u64t acc2[8][2];
    #pragma unroll
    for (int i = 0; i < 8; i++) { acc2[i][0] = 0ull; acc2[i][1] = 0ull; }

    for (int k0 = kb; k0 < ke; k0 += 32) {
        float4 a[4];
        #pragma unroll
        for (int c = 0; c < 4; c++)
            a[c] = *(const float4*)(A + (size_t)(m0 + ar) * K + k0 + ac + (c << 2));
        float4 b0 = *(const float4*)(B + (size_t)(k0 + br) * 64 + bc);
        float4 b1 = *(const float4*)(B + (size_t)(k0 + br) * 64 + bc + 32);
        __syncthreads();
        #pragma unroll
        for (int c = 0; c < 4; c++) {
            As[ac + (c << 2) + 0][ar] = a[c].x;
            As[ac + (c << 2) + 1][ar] = a[c].y;
            As[ac + (c << 2) + 2][ar] = a[c].z;
            As[ac + (c << 2) + 3][ar] = a[c].w;
        }
        *(float4*)&Bs[br][bc]      = b0;
        *(float4*)&Bs[br][bc + 32] = b1;
        __syncthreads();
        #pragma unroll
        for (int k = 0; k < 32; k++) {
            float4 av0 = *(const float4*)&As[k][ry];
            float4 av1 = *(const float4*)&As[k][ry + 4];
            float4 bv  = *(const float4*)&Bs[k][rxc];
            u64t bp0 = ((const u64t*)&bv)[0], bp1 = ((const u64t*)&bv)[1];
            float aa[8] = {av0.x, av0.y, av0.z, av0.w, av1.x, av1.y, av1.z, av1.w};
            #pragma unroll
            for (int i = 0; i < 8; i++) {
                u64t ai = bcast2(aa[i]);
                fma2(acc2[i][0], ai, bp0);
                fma2(acc2[i][1], ai, bp1);
            }
        }
    }
    int r = m0 + ry;
    #pragma unroll
    for (int i = 0; i < 8; i++) {
        float2 v0 = unpack2(acc2[i][0]);
        float2 v1 = unpack2(acc2[i][1]);
        float4 v = make_float4(v0.x, v0.y, v1.x, v1.y);
        *(float4*)(part + (size_t)s * M * 64 + (size_t)(r + i) * 64 + rxc) = v;
    }
}

__global__ void splitk_reduce_kernel(const float* __restrict__ part, const float* __restrict__ bias,
                                     float* __restrict__ C, int M, int S, int relu)
{
    int idx = blockIdx.x * 256 + threadIdx.x;
    if (idx >= M * 64) return;
    float s = 0.f;
    for (int p = 0; p < S; p++) s += part[(size_t)p * M * 64 + idx];
    if (bias) s += bias[idx & 63];
    if (relu) s = fmaxf(s, 0.f);
    C[idx] = s;
}

__global__ void cs_reduce_kernel(const float* __restrict__ CSP, float* __restrict__ CS)
{
    int m = blockIdx.y;
    int j = blockIdx.x * 256 + threadIdx.x;
    float s = 0.f;
    #pragma unroll
    for (int p = 0; p < 32; p++) s += CSP[((size_t)m * 32 + p) * NT + j];
    CS[m * NT + j] = s;
}

__global__ void coefs_kernel(const float* __restrict__ sgw, const float* __restrict__ ffw,
                             const float* __restrict__ f4w,
                             const float* __restrict__ cs, float* __restrict__ coef)
{
    int j = blockIdx.x * 256 + threadIdx.x;
    float m2 = fmaxf(sgw[0], sgw[1]);
    float e0 = expf(sgw[0] - m2), e1 = expf(sgw[1] - m2);
    float sa0 = e0 / (e0 + e1), sa1 = e1 / (e0 + e1);
    float mf = fmaxf(ffw[0], ffw[1]);
    float f0 = expf(ffw[0] - mf), f1 = expf(ffw[1] - mf);
    float fa0 = f0 / (f0 + f1), fa1 = f1 / (f0 + f1);
    float m4 = fmaxf(fmaxf(f4w[0], f4w[1]), fmaxf(f4w[2], f4w[3]));
    float w0 = expf(f4w[0] - m4), w1 = expf(f4w[1] - m4), w2 = expf(f4w[2] - m4), w3 = expf(f4w[3] - m4);
    float ws = w0 + w1 + w2 + w3;
    w0 /= ws; w1 /= ws; w2 /= ws; w3 /= ws;

    float csv[7];
    #pragma unroll
    for (int m = 0; m < 7; m++) csv[m] = cs[m * NT + j];
    float uP  = (csv[1] > 0.05f) ? 1.f : 0.f;
    float uQ  = (csv[2] > 0.05f) ? 1.f : 0.f;
    float uFA = (csv[3] > 0.05f) ? 1.f : 0.f;
    float uFS = (csv[4] > 0.05f) ? 1.f : 0.f;
    float uSA = (csv[5] > 0.05f) ? 1.f : 0.f;
    float uSS = (csv[6] > 0.05f) ? 1.f : 0.f;
    float dSem = fmaxf(sa0 * uP  + sa1 * uQ,  1e-12f);
    float dFp  = fmaxf(fa0 * uFA + fa1 * uFS, 1e-12f);
    float dSt  = fmaxf(fa0 * uSA + fa1 * uSS, 1e-12f);

    coef[0 * NT + j] = w0 / fmaxf(csv[0], 1e-12f);
    coef[1 * NT + j] = w1 * sa0 / (fmaxf(csv[1], 1e-12f) * dSem);
    coef[2 * NT + j] = w1 * sa1 / (fmaxf(csv[2], 1e-12f) * dSem);
    coef[3 * NT + j] = w2 * fa0 / (fmaxf(csv[3], 1e-12f) * dFp);
    coef[4 * NT + j] = w2 * fa1 / (fmaxf(csv[4], 1e-12f) * dFp);
    coef[5 * NT + j] = w3 * fa0 / (fmaxf(csv[5], 1e-12f) * dSt);
    coef[6 * NT + j] = w3 * fa1 / (fmaxf(csv[6], 1e-12f) * dSt);
}

// Triangular symmetric combine (see round-12 derivation).
__global__ void __launch_bounds__(256)
combine_tri_kernel(const float* __restrict__ G,  const float* __restrict__ P,
                   const float* __restrict__ Q,  const float* __restrict__ FA,
                   const float* __restrict__ FS, const float* __restrict__ SA,
                   const float* __restrict__ SS, const float* __restrict__ coef,
                   float* __restrict__ out, float* __restrict__ part)
{
    const int nb = 64;
    int idx = blockIdx.x;
    float nb2 = nb + 0.5f;
    int bi = (int)(nb2 - sqrtf(fmaxf(nb2 * nb2 - 2.0f * idx, 0.f)));
    if (bi < 0) bi = 0;
    if (bi > nb - 1) bi = nb - 1;
    while (bi > 0 && (bi * nb - (bi * (bi - 1)) / 2) > idx) bi--;
    while (((bi + 1) * nb - ((bi + 1) * bi) / 2) <= idx) bi++;
    int bj = bi + (idx - (bi * nb - (bi * (bi - 1)) / 2));

    __shared__ float S[64][65];
    int row = threadIdx.x >> 2;
    int cc  = (threadIdx.x & 3) << 4;
    int gi  = bi * 64 + row;
    int gj  = bj * 64 + cc;

    float cfi[7];
    #pragma unroll
    for (int m = 0; m < 7; m++) cfi[m] = coef[m * NT + gi];

    float rsum = 0.f;
    #pragma unroll
    for (int c4 = 0; c4 < 16; c4 += 4) {
        size_t e = (size_t)gi * NT + gj + c4;
        float4 r = make_float4(0.f, 0.f, 0.f, 0.f);
#define ACC(buf, m) { float4 v = *(const float4*)((buf) + e);                     \
                      float4 k = *(const float4*)(coef + (m) * NT + gj + c4);     \
                      r.x = fmaf(k.x + cfi[m], v.x, r.x);                         \
                      r.y = fmaf(k.y + cfi[m], v.y, r.y);                         \
                      r.z = fmaf(k.z + cfi[m], v.z, r.z);                         \
                      r.w = fmaf(k.w + cfi[m], v.w, r.w); }
        ACC(G, 0) ACC(P, 1) ACC(Q, 2) ACC(FA, 3) ACC(FS, 4) ACC(SA, 5) ACC(SS, 6)
#undef ACC
        *(float4*)(out + e) = r;
        S[row][cc + c4 + 0] = r.x;
        S[row][cc + c4 + 1] = r.y;
        S[row][cc + c4 + 2] = r.z;
        S[row][cc + c4 + 3] = r.w;
        rsum += r.x + r.y + r.z + r.w;
    }
    rsum += __shfl_xor_sync(0xffffffffu, rsum, 1);
    rsum += __shfl_xor_sync(0xffffffffu, rsum, 2);
    if ((threadIdx.x & 3) == 0)
        part[(size_t)bj * NT + gi] = rsum;

    if (bi != bj) {
        __syncthreads();
        float csum = 0.f;
        #pragma unroll
        for (int c4 = 0; c4 < 16; c4 += 4) {
            float4 v = make_float4(S[cc + c4 + 0][row], S[cc + c4 + 1][row],
                                   S[cc + c4 + 2][row], S[cc + c4 + 3][row]);
            *(float4*)(out + (size_t)(bj * 64 + row) * NT + bi * 64 + cc + c4) = v;
            csum += v.x + v.y + v.z + v.w;
        }
        csum += __shfl_xor_sync(0xffffffffu, csum, 1);
        csum += __shfl_xor_sync(0xffffffffu, csum, 2);
        if ((threadIdx.x & 3) == 0)
            part[(size_t)bi * NT + bj * 64 + row] = csum;
    }
}

__global__ void ct_reduce_kernel(const float* __restrict__ part, float* __restrict__ ct)
{
    int j = blockIdx.x * 256 + threadIdx.x;
    float s = 0.f;
    #pragma unroll
    for (int p = 0; p < 64; p++) s += part[(size_t)p * NT + j];
    ct[j] = s;
}

__global__ void scale_cols_kernel(float* __restrict__ A, const float* __restrict__ ct)
{
    size_t e = ((size_t)blockIdx.x * 256 + threadIdx.x) << 2;
    int j = (int)(e & (NT - 1));
    float4 v = *(float4*)(A + e);
    float4 c = *(const float4*)(ct + j);
    v.x /= fmaxf(c.x, 1e-12f); v.y /= fmaxf(c.y, 1e-12f);
    v.z /= fmaxf(c.z, 1e-12f); v.w /= fmaxf(c.w, 1e-12f);
    *(float4*)(A + e) = v;
}

__global__ void x1w2_kernel(const float* __restrict__ X1, const float* __restrict__ W2,
                            float* __restrict__ H2)
{
    int i = blockIdx.x * 256 + threadIdx.x;
    if (i >= NT) return;
    float s0 = 0.f, s1 = 0.f, s2 = 0.f;
    #pragma unroll 8
    for (int k = 0; k < COM; k++) {
        float x = X1[(size_t)i * COM + k];
        s0 = fmaf(x, W2[k * 3 + 0], s0);
        s1 = fmaf(x, W2[k * 3 + 1], s1);
        s2 = fmaf(x, W2[k * 3 + 2], s2);
    }
    H2[i * 3 + 0] = s0; H2[i * 3 + 1] = s1; H2[i * 3 + 2] = s2;
}

__global__ void logits_kernel(const float* __restrict__ A, const float* __restrict__ H2,
                              const float* __restrict__ b2, float* __restrict__ out)
{
    int i = blockIdx.x, tid = threadIdx.x;
    const float* row = A + (size_t)i * NT;
    float s0 = 0.f, s1 = 0.f, s2 = 0.f;
    for (int k = tid; k < NT; k += 256) {
        float a = row[k];
        s0 = fmaf(a, H2[k * 3 + 0], s0);
        s1 = fmaf(a, H2[k * 3 + 1], s1);
        s2 = fmaf(a, H2[k * 3 + 2], s2);
    }
    #pragma unroll
    for (int o = 16; o; o >>= 1) {
        s0 += __shfl_xor_sync(0xffffffffu, s0, o);
        s1 += __shfl_xor_sync(0xffffffffu, s1, o);
        s2 += __shfl_xor_sync(0xffffffffu, s2, o);
    }
    __shared__ float sh[3][8];
    int w = tid >> 5, l = tid & 31;
    if (l == 0) { sh[0][w] = s0; sh[1][w] = s1; sh[2][w] = s2; }
    __syncthreads();
    if (tid == 0) {
        float x0 = 0.f, x1 = 0.f, x2 = 0.f;
        #pragma unroll
        for (int t = 0; t < 8; t++) { x0 += sh[0][t]; x1 += sh[1][t]; x2 += sh[2][t]; }
        x0 += b2[0]; x1 += b2[1]; x2 += b2[2];
        float m  = fmaxf(x0, fmaxf(x1, x2));
        float ls = logf(expf(x0 - m) + expf(x1 - m) + expf(x2 - m));
        out[i * 3 + 0] = x0 - m - ls;
        out[i * 3 + 1] = x1 - m - ls;
        out[i * 3 + 2] = x2 - m - ls;
    }
}

// ---------------- host orchestration (single stream) -------------------------

extern "C" void kernel_launch(void* const* d_in, const int* in_sizes, int n_in,
                              void* d_out, int out_size)
{
    const float* features  = (const float*)d_in[0];
    const float* adj_ori   = (const float*)d_in[1];
    const float* mp_pap    = (const float*)d_in[2];
    const float* mp_psp    = (const float*)d_in[3];
    const float* fgo_w     = (const float*)d_in[6];
    const float* fpo_w     = (const float*)d_in[7];
    const float* sgg_pap_w = (const float*)d_in[8];
    const float* sgg_psp_w = (const float*)d_in[9];
    const float* sg_agg_w  = (const float*)d_in[10];
    const float* f_agg_f_w = (const float*)d_in[11];
    const float* f_agg_w   = (const float*)d_in[12];
    const float* topo_W_a  = (const float*)d_in[13];
    const float* topo_b_a  = (const float*)d_in[14];
    const float* topo_W_s  = (const float*)d_in[15];
    const float* topo_b_s  = (const float*)d_in[16];
    const float* fgt_w_a   = (const float*)d_in[17];
    const float* fgt_w_s   = (const float*)d_in[18];
    const float* gcn_W1    = (const float*)d_in[19];
    const float* gcn_b1    = (const float*)d_in[20];
    const float* gcn_W2    = (const float*)d_in[21];
    const float* gcn_b2    = (const float*)d_in[22];
    (void)in_sizes; (void)n_in; (void)out_size;

    float* out   = (float*)d_out;
    float* NAdj  = out + (size_t)NT * NCLS;

    float* big = nullptr; float* sm = nullptr; int* ib = nullptr;
    __nv_bfloat16* b1p = nullptr; __nv_bfloat16* b2p = nullptr; __nv_bfloat16* b3p = nullptr;
    cudaGetSymbolAddress((void**)&big, g_big);
    cudaGetSymbolAddress((void**)&sm,  g_small);
    cudaGetSymbolAddress((void**)&ib,  g_ibuf);
    cudaGetSymbolAddress((void**)&b1p, g_bf1);
    cudaGetSymbolAddress((void**)&b2p, g_bf2);
    cudaGetSymbolAddress((void**)&b3p, g_bf3);

    // allow 73.7 KB dynamic smem for the TC sim kernel (attribute set, not an allocation)
    static int smemConfigured = 0;
    if (!smemConfigured) {
        cudaFuncSetAttribute(simgemm_tc_multi_kernel,
                             cudaFuncAttributeMaxDynamicSharedMemorySize, 2 * STG);
        smemConfigured = 1;
    }

    float* G   = big + 0ll * NT * NT;
    float* P   = big + 1ll * NT * NT;
    float* Q   = big + 2ll * NT * NT;
    float* FAb = big + 3ll * NT * NT;
    float* FSb = big + 4ll * NT * NT;
    float* SAb = big + 5ll * NT * NT;   // sim_r_A (full), then s_h_A (triangular)
    float* SSb = big + 6ll * NT * NT;

    float* SIMS  = sm + OFF_SIMS;
    float* FPA   = sm + OFF_FPA;
    float* FPS   = sm + OFF_FPS;
    float* THA   = sm + OFF_THA;
    float* THS   = sm + OFF_THS;
    float* SWA   = sm + OFF_SWA;
    float* SWS   = sm + OFF_SWS;
    float* H0    = sm + OFF_H0;
    float* X1    = sm + OFF_X1;
    float* H2    = sm + OFF_H2;
    float* CS    = sm + OFF_CS;
    float* COEF  = sm + OFF_COEF;
    float* CT    = sm + OFF_CT;
    float* PART2 = sm + OFF_PART2;
    float* CSP   = sm + OFF_CSP;
    float* SPART = sm + OFF_SPART;

    int* IDXA = ib + OFF_IDXA; int* CNTA = ib + OFF_CNTA;
    int* IDXS = ib + OFF_IDXS; int* CNTS = ib + OFF_CNTS;

    const size_t BUF = (size_t)NT * 256;
    const int TRI32 = 32 * 33 / 2;   // 528
    const int TRI64 = 64 * 65 / 2;   // 2080

    // ---- adjacency index lists + feature propagation (independent of sims) ----
    build_idx_kernel<<<NT, 128>>>(adj_ori, NT, NAr, IDXA, CNTA);
    build_idx_kernel<<<NT, 128>>>(adj_ori, NT + NAr, NSr, IDXS, CNTS);
    gather_sum_kernel<<<dim3(1, NT), 32>>>(features + (size_t)NT * FEAT, FEAT, IDXA, CNTA, FPA, FEAT);
    gather_sum_kernel<<<dim3(1, NT), 32>>>(features + (size_t)(NT + NAr) * FEAT, FEAT, IDXS, CNTS, FPS, FEAT);

    // ---- prep batch A: 7 jobs ----
    {
        PrepJobs pj;
        pj.j[0] = {features,                              fgo_w,     b1p + 0*BUF, b2p + 0*BUF, b3p + 0*BUF, NT,  FEAT};
        pj.j[1] = {features + (size_t)NT * FEAT,          fgo_w,     b1p + 1*BUF, b2p + 1*BUF, b3p + 1*BUF, NAr, FEAT};
        pj.j[2] = {mp_pap,                                sgg_pap_w, b1p + 2*BUF, b2p + 2*BUF, b3p + 2*BUF, NT,  MPD};
        pj.j[3] = {mp_psp,                                sgg_psp_w, b1p + 3*BUF, b2p + 3*BUF, b3p + 3*BUF, NT,  MPD};
        pj.j[4] = {features + (size_t)(NT + NAr) * FEAT,  fgo_w,     b1p + 4*BUF, b2p + 4*BUF, b3p + 4*BUF, NSr, FEAT};
        pj.j[5] = {FPA,                                   fpo_w,     b1p + 5*BUF, b2p + 5*BUF, b3p + 5*BUF, NT,  FEAT};
        pj.j[6] = {FPS,                                   fpo_w,     b1p + 6*BUF, b2p + 6*BUF, b3p + 6*BUF, NT,  FEAT};
        prep_norm_multi_kernel<<<dim3(NT / 4, 7), 128>>>(pj);
    }

    // ---- sim batch 1 (tensor cores): G, sim_r_A, P, Q, sim_r_S, f_h_A, f_h_S ----
    {
        SimJobs sj;
        sj.j[0] = {b1p + 0*BUF, b2p + 0*BUF, b3p + 0*BUF, G,    CSP + 0ll * 32 * NT, NT,  256, 32, 0.1f, 0};
        sj.j[1] = {b1p + 1*BUF, b2p + 1*BUF, b3p + 1*BUF, SAb,  nullptr,             NT,  256, 32, 0.1f, 1};
        sj.j[2] = {b1p + 2*BUF, b2p + 2*BUF, b3p + 2*BUF, P,    CSP + 1ll * 32 * NT, NT,  128, 32, 0.1f, 0};
        sj.j[3] = {b1p + 3*BUF, b2p + 3*BUF, b3p + 3*BUF, Q,    CSP + 2ll * 32 * NT, NT,  128, 32, 0.1f, 0};
        sj.j[4] = {b1p + 4*BUF, b2p + 4*BUF, b3p + 4*BUF, SIMS, nullptr,             NSr, 256, 8,  0.1f, 1};
        sj.j[5] = {b1p + 5*BUF, b2p + 5*BUF, b3p + 5*BUF, FAb,  CSP + 3ll * 32 * NT, NT,  256, 32, 0.2f, 0};
        sj.j[6] = {b1p + 6*BUF, b2p + 6*BUF, b3p + 6*BUF, FSb,  CSP + 4ll * 32 * NT, NT,  256, 32, 0.2f, 0};
        simgemm_tc_multi_kernel<<<dim3(TRI32, 7), 256, 2 * STG>>>(sj);
    }

    // ---- topo chains (A then S) ----
    gemm128_splitk_kernel<<<dim3(NT / 128, 8), 256>>>(SAb, topo_W_a, SPART, NT, NAr, NAr / 8);
    splitk_reduce_kernel<<<(NT * 64) / 256, 256>>>(SPART, nullptr, SWA, NT, 8, 0);
    gather64b_kernel<<<NT, 64>>>(SWA, IDXA, CNTA, topo_b_a, THA);
    gemm128_splitk_kernel<<<dim3(NSr / 128, 8), 256>>>(SIMS, topo_W_s, SPART, NSr, NSr, NSr / 8);
    splitk_reduce_kernel<<<(NSr * 64) / 256, 256>>>(SPART, nullptr, SWS, NSr, 8, 0);
    gather64b_kernel<<<NT, 64>>>(SWS, IDXS, CNTS, topo_b_s, THS);

    // ---- prep batch B: 2 jobs ----
    {
        PrepJobs pj;
        pj.j[0] = {THA, fgt_w_a, b1p + 2*BUF, b2p + 2*BUF, b3p + 2*BUF, NT, COM};
        pj.j[1] = {THS, fgt_w_s, b1p + 3*BUF, b2p + 3*BUF, b3p + 3*BUF, NT, COM};
        for (int t = 2; t < 7; t++) pj.j[t] = {THA, fgt_w_a, b1p + 2*BUF, b2p + 2*BUF, b3p + 2*BUF, 0, COM};
        prep_norm_multi_kernel<<<dim3(NT / 4, 2), 128>>>(pj);
    }

    // ---- sim batch 2: s_h_A, s_h_S (triangular-only stores) ----
    {
        SimJobs sj;
        sj.j[0] = {b1p + 2*BUF, b2p + 2*BUF, b3p + 2*BUF, SAb, CSP + 5ll * 32 * NT, NT, 128, 32, 0.1f, 0};
        sj.j[1] = {b1p + 3*BUF, b2p + 3*BUF, b3p + 3*BUF, SSb, CSP + 6ll * 32 * NT, NT, 128, 32, 0.1f, 0};
        for (int t = 2; t < 7; t++) sj.j[t] = {b1p + 2*BUF, b2p + 2*BUF, b3p + 2*BUF, nullptr, nullptr, 0, 16, 0, 0.1f, 0};
        simgemm_tc_multi_kernel<<<dim3(TRI32, 2), 256, 2 * STG>>>(sj);
    }

    // ---- GCN first half (independent) ----
    gemm_n64_kernel<<<NT / 64, 256>>>(features, gcn_W1, nullptr, H0, NT, FEAT, 0);

    // ---- fused channel attention (triangular symmetric combine) ----
    cs_reduce_kernel<<<dim3(NT / 256, 7), 256>>>(CSP, CS);
    coefs_kernel<<<NT / 256, 256>>>(sg_agg_w, f_agg_f_w, f_agg_w, CS, COEF);
    combine_tri_kernel<<<TRI64, 256>>>(G, P, Q, FAb, FSb, SAb, SSb, COEF, NAdj, PART2);
    ct_reduce_kernel<<<NT / 256, 256>>>(PART2, CT);
    scale_cols_kernel<<<(NT * NT) / 1024, 256>>>(NAdj, CT);

    // ---- GCN second half ----
    gemm128_splitk_kernel<<<dim3(NT / 128, 8), 256>>>(NAdj, H0, SPART, NT, NT, NT / 8);
    splitk_reduce_kernel<<<(NT * 64) / 256, 256>>>(SPART, gcn_b1, X1, NT, 8, 1);
    x1w2_kernel<<<NT / 256, 256>>>(X1, gcn_W2, H2);
    logits_kernel<<<NT, 256>>>(NAdj, H2, gcn_b2, out);
}